// round 12
// baseline (speedup 1.0000x reference)
#include <cuda_runtime.h>
#include <cuda_bf16.h>
#include <cstdint>

#define S_LEN 128
#define T_LEN 128
#define BATCH 16
#define VOCAB 32000

// ---------------- static scratch ----------------
__device__ float g_x[2048 * 1024];       // embeddings / layer inputs
__device__ float g_xproj[2048 * 4096];   // precomputed x@Wih^T + b
__device__ float g_y[2048 * 1024];       // encoder layer0 concat outputs
__device__ float g_h0seq[2048 * 1024];   // decoder layer0 hidden sequence
__device__ float g_h1seq[2048 * 1024];   // decoder layer1 hidden sequence
__device__ float g_hA[16384], g_hB[16384];   // encoder h ping-pong [dir][b][512]
__device__ float g_encC[16384];              // encoder c
__device__ float g_dhA[16384], g_dhB[16384]; // decoder L0 h ping-pong [b][1024]
__device__ float g_dhC[16384], g_dhD[16384]; // decoder L1 h ping-pong
__device__ float g_dc0[16384], g_dc1[16384]; // decoder c per layer
// bf16-split buffers
__device__ __nv_bfloat16 g_Ah[2048 * 1024];
__device__ __nv_bfloat16 g_Al[2048 * 1024];
__device__ __nv_bfloat16 g_Wh[32768 * 1024];
__device__ __nv_bfloat16 g_Wl[32768 * 1024];
// grid barrier state
__device__ unsigned g_barc = 0;
__device__ unsigned g_barg = 0;

// ---------------- grid-wide barrier (all blocks co-resident) ----------------
__device__ __forceinline__ void grid_barrier() {
    __threadfence();
    __syncthreads();
    if (threadIdx.x == 0) {
        volatile unsigned* vg = &g_barg;
        const unsigned gen = *vg;
        if (atomicAdd(&g_barc, 1u) == gridDim.x - 1u) {
            g_barc = 0u;
            __threadfence();
            atomicAdd((unsigned*)&g_barg, 1u);
        } else {
            while (*vg == gen) { __nanosleep(64); }
        }
    }
    __syncthreads();
}

// ---------------- embedding gathers ----------------
__global__ void enc_embed_kernel(const float* __restrict__ emb,
                                 const int* __restrict__ src, float* __restrict__ dst) {
    int r = blockIdx.x, t = r >> 4, b = r & 15;
    int tok = src[b * S_LEN + t];
    ((float4*)(dst + (size_t)r * 1024))[threadIdx.x] =
        ((const float4*)(emb + (size_t)tok * 1024))[threadIdx.x];
}
__global__ void dec_embed_kernel(const float* __restrict__ emb,
                                 const int* __restrict__ tgt, float* __restrict__ dst) {
    int r = blockIdx.x, s = r >> 4, b = r & 15;
    int tok = (s == 0) ? 1 : tgt[b * T_LEN + s];
    ((float4*)(dst + (size_t)r * 1024))[threadIdx.x] =
        ((const float4*)(emb + (size_t)tok * 1024))[threadIdx.x];
}

// ---------------- fp32 -> (hi, lo) bf16 split ----------------
__global__ void split_kernel(const float2* __restrict__ s,
                             __nv_bfloat162* __restrict__ h,
                             __nv_bfloat162* __restrict__ l, int n2) {
    int i = blockIdx.x * 256 + threadIdx.x;
    if (i < n2) {
        float2 v = s[i];
        __nv_bfloat16 hx = __float2bfloat16(v.x);
        __nv_bfloat16 hy = __float2bfloat16(v.y);
        float lx = v.x - __bfloat162float(hx);
        float ly = v.y - __bfloat162float(hy);
        __nv_bfloat162 hh; hh.x = hx; hh.y = hy;
        __nv_bfloat162 ll; ll.x = __float2bfloat16(lx); ll.y = __float2bfloat16(ly);
        h[i] = hh;
        l[i] = ll;
    }
}

// ---------------- persistent LSTM chain ----------------
// 1024 threads / 32 warps; warp = (local unit, batch-quarter).
// Each warp: 4 gate rows x 4 batches; lanes split K; fold reduction (16 vals).
// 8 warps/SMSP for latency hiding.
template <int U, int NDIR>
__global__ void __launch_bounds__(1024, 1)
lstm_chain_kernel(const float* __restrict__ Whh,  // [NDIR][4U][U]
                  float* __restrict__ h_a,        // ping-pong [NDIR][B][U]
                  float* __restrict__ h_b,
                  float* __restrict__ c,          // [NDIR][B][U] in-place
                  const float* __restrict__ xpbase, // [nsteps][B][4096]
                  float* __restrict__ ybase,      // optional [nsteps][B][1024]
                  int nsteps) {
    extern __shared__ float hs[];
    const int tid = threadIdx.x, warp = tid >> 5, lane = tid & 31;
    const int gu = blockIdx.x * 8 + (warp >> 2);  // global unit id
    const int bq = warp & 3;                      // batch quarter
    const int dir = (NDIR == 2) ? (gu / U) : 0;
    const int u = gu - dir * U;

    const float* W = Whh + (size_t)dir * 4 * U * U;
    const float* Wr0 = W + (size_t)(0 * U + u) * U;
    const float* Wr1 = W + (size_t)(1 * U + u) * U;
    const float* Wr2 = W + (size_t)(2 * U + u) * U;
    const float* Wr3 = W + (size_t)(3 * U + u) * U;
    constexpr int ITERS = U >> 7;

    for (int j = 0; j < nsteps; ++j) {
        const float* hin = (j & 1) ? h_b : h_a;
        float* hout = (j & 1) ? h_a : h_b;
        {
            const float4* src4 = (const float4*)(hin + (size_t)dir * BATCH * U);
            float4* dst4 = (float4*)hs;
            for (int i = tid; i < BATCH * U / 4; i += 1024) dst4[i] = __ldcg(src4 + i);
        }
        __syncthreads();

        // v[g*4 + bl]: gate g, batch (bq*4+bl)
        float v[16];
#pragma unroll
        for (int i = 0; i < 16; ++i) v[i] = 0.f;

#pragma unroll
        for (int q = 0; q < ITERS; ++q) {
            const int kb = (q << 7) + (lane << 2);
            const float4 w0 = *(const float4*)(Wr0 + kb);
            const float4 w1 = *(const float4*)(Wr1 + kb);
            const float4 w2 = *(const float4*)(Wr2 + kb);
            const float4 w3 = *(const float4*)(Wr3 + kb);
#pragma unroll
            for (int bl = 0; bl < 4; ++bl) {
                const float4 h4 = *(const float4*)(hs + (bq * 4 + bl) * U + kb);
                v[bl]      += w0.x*h4.x + w0.y*h4.y + w0.z*h4.z + w0.w*h4.w;
                v[4 + bl]  += w1.x*h4.x + w1.y*h4.y + w1.z*h4.z + w1.w*h4.w;
                v[8 + bl]  += w2.x*h4.x + w2.y*h4.y + w2.z*h4.z + w2.w*h4.w;
                v[12 + bl] += w3.x*h4.x + w3.y*h4.y + w3.z*h4.z + w3.w*h4.w;
            }
        }

        // pair-fold 16 values over lane bits 0..3, then close k-reduction over bit 4
#pragma unroll
        for (int w = 8; w >= 1; w >>= 1) {
#pragma unroll
            for (int i = 0; i < 8; ++i) {
                if (i < w) {
                    const float aa = v[i], bb = v[i + w];
                    const bool hi = (lane & w) != 0;
                    const float keep = hi ? bb : aa;
                    const float send = hi ? aa : bb;
                    v[i] = keep + __shfl_xor_sync(0xffffffffu, send, w);
                }
            }
        }
        v[0] += __shfl_xor_sync(0xffffffffu, v[0], 16);
        const float r = v[0];                 // lane l holds index (l & 15)
        const int bl = lane & 3;
        const float zi_g = __shfl_sync(0xffffffffu, r, bl);
        const float zf_g = __shfl_sync(0xffffffffu, r, bl + 4);
        const float zg_g = __shfl_sync(0xffffffffu, r, bl + 8);
        const float zo_g = __shfl_sync(0xffffffffu, r, bl + 12);

        if (lane < 4) {
            const int b = bq * 4 + lane;
            const float* xp;
            float* y = nullptr;
            if (NDIR == 2 && dir == 1) {
                const int jr = nsteps - 1 - j;
                xp = xpbase + (size_t)jr * 65536 + 2048 + (size_t)b * 4096;
                if (ybase) y = ybase + (size_t)jr * 16384 + (size_t)b * 1024 + 512 + u;
            } else {
                xp = xpbase + (size_t)j * 65536 + (size_t)b * 4096;
                if (ybase) y = ybase + (size_t)j * 16384 + (size_t)b * 1024 + u;
            }
            const float zi = zi_g + xp[0 * U + u];
            const float zf = zf_g + xp[1 * U + u];
            const float zg = zg_g + xp[2 * U + u];
            const float zo = zo_g + xp[3 * U + u];
            const float ig = 1.f / (1.f + __expf(-zi));
            const float fg = 1.f / (1.f + __expf(-zf));
            const float gg = tanhf(zg);
            const float og = 1.f / (1.f + __expf(-zo));
            const size_t idx = (size_t)dir * BATCH * U + (size_t)b * U + u;
            const float cn = fg * c[idx] + ig * gg;
            c[idx] = cn;
            const float hn = og * tanhf(cn);
            hout[idx] = hn;
            if (y) *y = hn;
        }
        if (j + 1 < nsteps) grid_barrier();
    }
}

// ---------------- bf16-split NT GEMM via mma.sync, cp.async double-buffered ----------------
#define LDSM4(d0,d1,d2,d3,addr) \
    asm volatile("ldmatrix.sync.aligned.m8n8.x4.shared.b16 {%0,%1,%2,%3}, [%4];" \
                 : "=r"(d0),"=r"(d1),"=r"(d2),"=r"(d3) : "r"(addr))
#define LDSM2(d0,d1,addr) \
    asm volatile("ldmatrix.sync.aligned.m8n8.x2.shared.b16 {%0,%1}, [%2];" \
                 : "=r"(d0),"=r"(d1) : "r"(addr))
#define MMA16816(c0,c1,c2,c3,a0,a1,a2,a3,b0,b1) \
    asm volatile("mma.sync.aligned.m16n8k16.row.col.f32.bf16.bf16.f32 " \
                 "{%0,%1,%2,%3},{%4,%5,%6,%7},{%8,%9},{%0,%1,%2,%3};" \
                 : "+f"(c0),"+f"(c1),"+f"(c2),"+f"(c3) \
                 : "r"(a0),"r"(a1),"r"(a2),"r"(a3),"r"(b0),"r"(b1))
#define CP16(dst, src) \
    asm volatile("cp.async.cg.shared.global [%0], [%1], 16;" \
                 :: "r"(dst), "l"(src) : "memory")
#define CP_COMMIT() asm volatile("cp.async.commit_group;" ::: "memory")
#define CP_WAIT1()  asm volatile("cp.async.wait_group 1;" ::: "memory")
#define CP_WAIT0()  asm volatile("cp.async.wait_group 0;" ::: "memory")

#define SPAD 40
#define TILE_B (128 * SPAD * 2)          // bytes per array tile (10240)
#define STAGE_B (4 * TILE_B)             // bytes per stage (40960)
#define GEMM_SMEM (2 * STAGE_B)          // 81920

__device__ __forceinline__ void store_c(float* __restrict__ C, int m, int cc,
                                        float v0, float v1, int M, int N, int fcmode) {
    if (m >= M) return;
    float2 v; v.x = v0; v.y = v1;
    if (fcmode) {
        const int b = m & 15, t = (m >> 4) + 1;
        *(float2*)&C[(size_t)b * T_LEN * VOCAB + (size_t)t * VOCAB + cc] = v;
    } else {
        *(float2*)&C[(size_t)m * N + cc] = v;
    }
}

__global__ void __launch_bounds__(256, 2)
gemm_bf16x3_kernel(const __nv_bfloat16* __restrict__ Ah, const __nv_bfloat16* __restrict__ Al,
                   const __nv_bfloat16* __restrict__ Bh, const __nv_bfloat16* __restrict__ Bl,
                   const float* __restrict__ bias, float* __restrict__ C,
                   int M, int N, int K, int fcmode) {
    extern __shared__ __nv_bfloat16 sm[];  // [2 stages][4 arrays][128*SPAD]
    const int tid = threadIdx.x, warp = tid >> 5, lane = tid & 31;
    const int wm = warp >> 2, wn = warp & 3;
    const int m0 = blockIdx.y * 128, n0 = blockIdx.x * 128;
    const int lrow = tid >> 2;
    const int lcol = (tid & 3) << 3;

    const uint32_t smbase = (uint32_t)__cvta_generic_to_shared(sm);

    float acc[4][4][4];
#pragma unroll
    for (int i = 0; i < 4; ++i)
#pragma unroll
        for (int j = 0; j < 4; ++j)
#pragma unroll
            for (int q = 0; q < 4; ++q) acc[i][j][q] = 0.f;

    const int a_row = wm * 64 + (lane & 15);
    const int a_csel = (lane >> 4) << 3;
    const int b_row = wn * 32 + (lane & 7);
    const int b_csel = lane & 8;
    const int NT = K >> 5;

    auto issue_stage = [&](int kt, int s) {
        const int kc = kt << 5;
        const uint32_t stg = smbase + (uint32_t)(s * STAGE_B);
#pragma unroll
        for (int i = 0; i < 2; ++i) {
            const int r = lrow + i * 64;
            const size_t ga = (size_t)(m0 + r) * K + kc + lcol;
            const size_t gb = (size_t)(n0 + r) * K + kc + lcol;
            const uint32_t so = (uint32_t)(r * SPAD + lcol) * 2;
            CP16(stg + 0 * TILE_B + so, Ah + ga);
            CP16(stg + 1 * TILE_B + so, Al + ga);
            CP16(stg + 2 * TILE_B + so, Bh + gb);
            CP16(stg + 3 * TILE_B + so, Bl + gb);
        }
    };

    issue_stage(0, 0);
    CP_COMMIT();

    for (int kt = 0; kt < NT; ++kt) {
        const int s = kt & 1;
        if (kt + 1 < NT) {
            issue_stage(kt + 1, s ^ 1);
            CP_COMMIT();
            CP_WAIT1();
        } else {
            CP_WAIT0();
        }
        __syncthreads();

        const uint32_t stg = smbase + (uint32_t)(s * STAGE_B);
#pragma unroll
        for (int h = 0; h < 2; ++h) {
            const int kk = h << 4;
            uint32_t afh[4][4], afl[4][4], bfh[4][2], bfl[4][2];
#pragma unroll
            for (int mi = 0; mi < 4; ++mi) {
                const uint32_t off = (uint32_t)(((a_row + mi * 16) * SPAD + kk + a_csel) * 2);
                LDSM4(afh[mi][0], afh[mi][1], afh[mi][2], afh[mi][3], stg + 0 * TILE_B + off);
                LDSM4(afl[mi][0], afl[mi][1], afl[mi][2], afl[mi][3], stg + 1 * TILE_B + off);
            }
#pragma unroll
            for (int ni = 0; ni < 4; ++ni) {
                const uint32_t off = (uint32_t)(((b_row + ni * 8) * SPAD + kk + b_csel) * 2);
                LDSM2(bfh[ni][0], bfh[ni][1], stg + 2 * TILE_B + off);
                LDSM2(bfl[ni][0], bfl[ni][1], stg + 3 * TILE_B + off);
            }
#pragma unroll
            for (int mi = 0; mi < 4; ++mi)
#pragma unroll
                for (int ni = 0; ni < 4; ++ni) {
                    float* c4 = acc[mi][ni];
                    MMA16816(c4[0], c4[1], c4[2], c4[3],
                             afh[mi][0], afh[mi][1], afh[mi][2], afh[mi][3],
                             bfh[ni][0], bfh[ni][1]);
                    MMA16816(c4[0], c4[1], c4[2], c4[3],
                             afh[mi][0], afh[mi][1], afh[mi][2], afh[mi][3],
                             bfl[ni][0], bfl[ni][1]);
                    MMA16816(c4[0], c4[1], c4[2], c4[3],
                             afl[mi][0], afl[mi][1], afl[mi][2], afl[mi][3],
                             bfh[ni][0], bfh[ni][1]);
                }
        }
        __syncthreads();
    }

    const int g = lane >> 2, tc = lane & 3;
#pragma unroll
    for (int mi = 0; mi < 4; ++mi) {
#pragma unroll
        for (int ni = 0; ni < 4; ++ni) {
            const int r0 = m0 + wm * 64 + mi * 16 + g;
            const int cc = n0 + wn * 32 + ni * 8 + tc * 2;
            const float bb0 = bias[cc], bb1 = bias[cc + 1];
            store_c(C, r0,     cc, acc[mi][ni][0] + bb0, acc[mi][ni][1] + bb1, M, N, fcmode);
            store_c(C, r0 + 8, cc, acc[mi][ni][2] + bb0, acc[mi][ni][3] + bb1, M, N, fcmode);
        }
    }
}

// encoder [dir][b][512] -> decoder [b][1024]
__global__ void concat_hc_kernel(const float* __restrict__ hsrc, const float* __restrict__ csrc,
                                 float* __restrict__ hdst, float* __restrict__ cdst) {
    const int idx = blockIdx.x * 256 + threadIdx.x;
    const int b = idx >> 10, col = idx & 1023;
    const int dir = col >> 9, u = col & 511;
    const int s = dir * 8192 + b * 512 + u;
    hdst[idx] = hsrc[s];
    cdst[idx] = csrc[s];
}

__global__ void zero_t0_kernel(float* __restrict__ out) {
    const int idx = blockIdx.x * 256 + threadIdx.x;
    if (idx < 16 * VOCAB) {
        const int b = idx / VOCAB, v = idx - b * VOCAB;
        out[(size_t)b * T_LEN * VOCAB + v] = 0.f;
    }
}

// ---------------- driver ----------------
extern "C" void kernel_launch(void* const* d_in, const int* in_sizes, int n_in,
                              void* d_out, int out_size) {
    (void)in_sizes; (void)n_in; (void)out_size;
    const int*   src       = (const int*)d_in[0];
    const int*   tgt       = (const int*)d_in[1];
    const float* enc_embed = (const float*)d_in[3];
    const float* enc_Wih   = (const float*)d_in[4];
    const float* enc_Whh   = (const float*)d_in[5];
    const float* enc_b     = (const float*)d_in[6];
    const float* dec_embed = (const float*)d_in[7];
    const float* dec_Wih   = (const float*)d_in[8];
    const float* dec_Whh   = (const float*)d_in[9];
    const float* dec_b     = (const float*)d_in[10];
    const float* fc_W      = (const float*)d_in[11];
    const float* fc_b      = (const float*)d_in[12];
    float* out = (float*)d_out;

    float *x, *xp, *y, *h0s, *h1s, *hA, *hB, *eC, *dA, *dB, *dC, *dD, *c0, *c1;
    __nv_bfloat16 *Ah, *Al, *Wh, *Wl;
    cudaGetSymbolAddress((void**)&x, g_x);
    cudaGetSymbolAddress((void**)&xp, g_xproj);
    cudaGetSymbolAddress((void**)&y, g_y);
    cudaGetSymbolAddress((void**)&h0s, g_h0seq);
    cudaGetSymbolAddress((void**)&h1s, g_h1seq);
    cudaGetSymbolAddress((void**)&hA, g_hA);
    cudaGetSymbolAddress((void**)&hB, g_hB);
    cudaGetSymbolAddress((void**)&eC, g_encC);
    cudaGetSymbolAddress((void**)&dA, g_dhA);
    cudaGetSymbolAddress((void**)&dB, g_dhB);
    cudaGetSymbolAddress((void**)&dC, g_dhC);
    cudaGetSymbolAddress((void**)&dD, g_dhD);
    cudaGetSymbolAddress((void**)&c0, g_dc0);
    cudaGetSymbolAddress((void**)&c1, g_dc1);
    cudaGetSymbolAddress((void**)&Ah, g_Ah);
    cudaGetSymbolAddress((void**)&Al, g_Al);
    cudaGetSymbolAddress((void**)&Wh, g_Wh);
    cudaGetSymbolAddress((void**)&Wl, g_Wl);

    cudaFuncSetAttribute(lstm_chain_kernel<512, 2>,
                         cudaFuncAttributeMaxDynamicSharedMemorySize, 32768);
    cudaFuncSetAttribute(lstm_chain_kernel<1024, 1>,
                         cudaFuncAttributeMaxDynamicSharedMemorySize, 65536);
    cudaFuncSetAttribute(gemm_bf16x3_kernel,
                         cudaFuncAttributeMaxDynamicSharedMemorySize, GEMM_SMEM);

    auto splitN = [](const float* s, __nv_bfloat16* h, __nv_bfloat16* l, int n) {
        int n2 = n >> 1;
        split_kernel<<<(n2 + 255) / 256, 256>>>((const float2*)s,
                                                (__nv_bfloat162*)h, (__nv_bfloat162*)l, n2);
    };

    // ===== Encoder =====
    enc_embed_kernel<<<2048, 256>>>(enc_embed, src, x);
    for (int l = 0; l < 2; ++l) {
        cudaMemsetAsync(hA, 0, 16384 * sizeof(float));
        cudaMemsetAsync(eC, 0, 16384 * sizeof(float));
        const float* Ain = (l == 0) ? x : y;
        splitN(Ain, Ah, Al, 2048 * 1024);
        splitN(enc_Wih + (size_t)l * 4096 * 1024, Wh, Wl, 4096 * 1024);
        gemm_bf16x3_kernel<<<dim3(32, 16), 256, GEMM_SMEM>>>(
            Ah, Al, Wh, Wl, enc_b + l * 4096, xp, 2048, 4096, 1024, 0);
        const float* Whh_l = enc_Whh + (size_t)l * 2 * 2048 * 512;
        lstm_chain_kernel<512, 2><<<128, 1024, 32768>>>(
            Whh_l, hA, hB, eC, xp, (l == 0) ? y : nullptr, 128);
        float* hdst = (l == 0) ? dA : dC;
        float* cdst = (l == 0) ? c0 : c1;
        concat_hc_kernel<<<64, 256>>>(hA, eC, hdst, cdst);
    }

    // ===== Decoder =====
    dec_embed_kernel<<<2032, 256>>>(dec_embed, tgt, x);
    // layer 0
    splitN(x, Ah, Al, 2032 * 1024);
    splitN(dec_Wih, Wh, Wl, 4096 * 1024);
    gemm_bf16x3_kernel<<<dim3(32, 16), 256, GEMM_SMEM>>>(
        Ah, Al, Wh, Wl, dec_b, xp, 2032, 4096, 1024, 0);
    lstm_chain_kernel<1024, 1><<<128, 1024, 65536>>>(
        dec_Whh, dA, dB, c0, xp, h0s, 127);
    // layer 1
    splitN(h0s, Ah, Al, 2032 * 1024);
    splitN(dec_Wih + (size_t)4096 * 1024, Wh, Wl, 4096 * 1024);
    gemm_bf16x3_kernel<<<dim3(32, 16), 256, GEMM_SMEM>>>(
        Ah, Al, Wh, Wl, dec_b + 4096, xp, 2032, 4096, 1024, 0);
    lstm_chain_kernel<1024, 1><<<128, 1024, 65536>>>(
        dec_Whh + (size_t)4096 * 1024, dC, dD, c1, xp, h1s, 127);

    // ===== Output =====
    zero_t0_kernel<<<2000, 256>>>(out);
    splitN(h1s, Ah, Al, 2032 * 1024);
    splitN(fc_W, Wh, Wl, 32000 * 1024);
    gemm_bf16x3_kernel<<<dim3(250, 16), 256, GEMM_SMEM>>>(
        Ah, Al, Wh, Wl, fc_b, out, 2032, VOCAB, 1024, 1);
}

// round 13
// speedup vs baseline: 1.1374x; 1.1374x over previous
#include <cuda_runtime.h>
#include <cuda_bf16.h>
#include <cstdint>

#define S_LEN 128
#define T_LEN 128
#define BATCH 16
#define VOCAB 32000

// ---------------- static scratch ----------------
__device__ float g_x[2048 * 1024];       // embeddings / layer inputs
__device__ float g_xproj[2048 * 4096];   // precomputed x@Wih^T + b
__device__ float g_y[2048 * 1024];       // encoder layer0 concat outputs
__device__ float g_h0seq[2048 * 1024];   // decoder layer0 hidden sequence
__device__ float g_h1seq[2048 * 1024];   // decoder layer1 hidden sequence
__device__ float g_hA[16384], g_hB[16384];   // encoder h ping-pong [dir][b][512]
__device__ float g_encC[16384];              // encoder c
__device__ float g_dhA[16384], g_dhB[16384]; // decoder L0 h ping-pong [b][1024]
__device__ float g_dhC[16384], g_dhD[16384]; // decoder L1 h ping-pong
__device__ float g_dc0[16384], g_dc1[16384]; // decoder c per layer
// bf16-split buffers
__device__ __nv_bfloat16 g_Ah[2048 * 1024];
__device__ __nv_bfloat16 g_Al[2048 * 1024];
__device__ __nv_bfloat16 g_Wh[32768 * 1024];
__device__ __nv_bfloat16 g_Wl[32768 * 1024];
// grid barrier state
__device__ unsigned g_barc = 0;
__device__ unsigned g_barg = 0;

// ---------------- grid-wide barrier (all blocks co-resident) ----------------
__device__ __forceinline__ void grid_barrier() {
    __threadfence();
    __syncthreads();
    if (threadIdx.x == 0) {
        volatile unsigned* vg = &g_barg;
        const unsigned gen = *vg;
        if (atomicAdd(&g_barc, 1u) == gridDim.x - 1u) {
            g_barc = 0u;
            __threadfence();
            atomicAdd((unsigned*)&g_barg, 1u);
        } else {
            while (*vg == gen) { }   // tight spin: ~L2 latency granularity
        }
    }
    __syncthreads();
}

// ---------------- embedding gathers ----------------
__global__ void enc_embed_kernel(const float* __restrict__ emb,
                                 const int* __restrict__ src, float* __restrict__ dst) {
    int r = blockIdx.x, t = r >> 4, b = r & 15;
    int tok = src[b * S_LEN + t];
    ((float4*)(dst + (size_t)r * 1024))[threadIdx.x] =
        ((const float4*)(emb + (size_t)tok * 1024))[threadIdx.x];
}
__global__ void dec_embed_kernel(const float* __restrict__ emb,
                                 const int* __restrict__ tgt, float* __restrict__ dst) {
    int r = blockIdx.x, s = r >> 4, b = r & 15;
    int tok = (s == 0) ? 1 : tgt[b * T_LEN + s];
    ((float4*)(dst + (size_t)r * 1024))[threadIdx.x] =
        ((const float4*)(emb + (size_t)tok * 1024))[threadIdx.x];
}

// ---------------- fp32 -> (hi, lo) bf16 split ----------------
__global__ void split_kernel(const float2* __restrict__ s,
                             __nv_bfloat162* __restrict__ h,
                             __nv_bfloat162* __restrict__ l, int n2) {
    int i = blockIdx.x * 256 + threadIdx.x;
    if (i < n2) {
        float2 v = s[i];
        __nv_bfloat16 hx = __float2bfloat16(v.x);
        __nv_bfloat16 hy = __float2bfloat16(v.y);
        float lx = v.x - __bfloat162float(hx);
        float ly = v.y - __bfloat162float(hy);
        __nv_bfloat162 hh; hh.x = hx; hh.y = hy;
        __nv_bfloat162 ll; ll.x = __float2bfloat16(lx); ll.y = __float2bfloat16(ly);
        h[i] = hh;
        l[i] = ll;
    }
}

// ---------------- persistent LSTM chain (R11 config + reg-c + xp prefetch) ----
// 512 threads / 16 warps; warp = (local unit, batch-half); lanes split K.
template <int U, int NDIR>
__global__ void __launch_bounds__(512, 1)
lstm_chain_kernel(const float* __restrict__ Whh,  // [NDIR][4U][U]
                  float* __restrict__ h_a,        // ping-pong [NDIR][B][U]
                  float* __restrict__ h_b,
                  float* __restrict__ c,          // [NDIR][B][U]
                  const float* __restrict__ xpbase, // [nsteps][B][4096]
                  float* __restrict__ ybase,      // optional [nsteps][B][1024]
                  int nsteps) {
    extern __shared__ float hs[];
    const int tid = threadIdx.x, warp = tid >> 5, lane = tid & 31;
    const int gu = blockIdx.x * 8 + (warp >> 1);
    const int bh = warp & 1;
    const int dir = (NDIR == 2) ? (gu / U) : 0;
    const int u = gu - dir * U;

    const float* W = Whh + (size_t)dir * 4 * U * U;
    const float* Wr0 = W + (size_t)(0 * U + u) * U;
    const float* Wr1 = W + (size_t)(1 * U + u) * U;
    const float* Wr2 = W + (size_t)(2 * U + u) * U;
    const float* Wr3 = W + (size_t)(3 * U + u) * U;
    constexpr int ITERS = U >> 7;

    // this lane's (b,u) state: c lives in a register across all steps
    const int b = bh * 8 + (lane & 7);
    const size_t cidx = (size_t)dir * BATCH * U + (size_t)b * U + u;
    float cr = (lane < 8) ? c[cidx] : 0.f;

    for (int j = 0; j < nsteps; ++j) {
        const float* hin = (j & 1) ? h_b : h_a;
        float* hout = (j & 1) ? h_a : h_b;

        // xp prefetch: issue early so L2 latency hides under the W loop
        const float* xp;
        float* y = nullptr;
        if (NDIR == 2 && dir == 1) {
            const int jr = nsteps - 1 - j;
            xp = xpbase + (size_t)jr * 65536 + 2048 + (size_t)b * 4096;
            if (ybase) y = ybase + (size_t)jr * 16384 + (size_t)b * 1024 + 512 + u;
        } else {
            xp = xpbase + (size_t)j * 65536 + (size_t)b * 4096;
            if (ybase) y = ybase + (size_t)j * 16384 + (size_t)b * 1024 + u;
        }
        float xpi = 0.f, xpf = 0.f, xpg = 0.f, xpo = 0.f;
        if (lane < 8) {
            xpi = __ldg(xp + 0 * U + u);
            xpf = __ldg(xp + 1 * U + u);
            xpg = __ldg(xp + 2 * U + u);
            xpo = __ldg(xp + 3 * U + u);
        }

        // reload h_prev into smem, L1-bypassed (other SMs wrote it last step)
        {
            const float4* src4 = (const float4*)(hin + (size_t)dir * BATCH * U);
            float4* dst4 = (float4*)hs;
            for (int i = tid; i < BATCH * U / 4; i += 512) dst4[i] = __ldcg(src4 + i);
        }
        __syncthreads();

        // v[g*8 + bl]: gate g, batch (bh*8+bl)
        float v[32];
#pragma unroll
        for (int i = 0; i < 32; ++i) v[i] = 0.f;

        int kb = lane << 2;
        float4 w0 = *(const float4*)(Wr0 + kb);
        float4 w1 = *(const float4*)(Wr1 + kb);
        float4 w2 = *(const float4*)(Wr2 + kb);
        float4 w3 = *(const float4*)(Wr3 + kb);
#pragma unroll
        for (int q = 0; q < ITERS; ++q) {
            const int kn = (q + 1 < ITERS) ? kb + 128 : kb;
            const float4 n0 = *(const float4*)(Wr0 + kn);
            const float4 n1 = *(const float4*)(Wr1 + kn);
            const float4 n2 = *(const float4*)(Wr2 + kn);
            const float4 n3 = *(const float4*)(Wr3 + kn);
#pragma unroll
            for (int bl = 0; bl < 8; ++bl) {
                const float4 h4 = *(const float4*)(hs + (bh * 8 + bl) * U + kb);
                v[bl]      += w0.x*h4.x + w0.y*h4.y + w0.z*h4.z + w0.w*h4.w;
                v[8 + bl]  += w1.x*h4.x + w1.y*h4.y + w1.z*h4.z + w1.w*h4.w;
                v[16 + bl] += w2.x*h4.x + w2.y*h4.y + w2.z*h4.z + w2.w*h4.w;
                v[24 + bl] += w3.x*h4.x + w3.y*h4.y + w3.z*h4.z + w3.w*h4.w;
            }
            w0 = n0; w1 = n1; w2 = n2; w3 = n3; kb = kn;
        }

        // pair-folding reduction: lane l ends with total of v-index l in v[0]
#pragma unroll
        for (int w = 16; w >= 1; w >>= 1) {
#pragma unroll
            for (int i = 0; i < 16; ++i) {
                if (i < w) {
                    const float aa = v[i], bb = v[i + w];
                    const bool hi = (lane & w) != 0;
                    const float keep = hi ? bb : aa;
                    const float send = hi ? aa : bb;
                    v[i] = keep + __shfl_xor_sync(0xffffffffu, send, w);
                }
            }
        }
        const float r = v[0];
        const int bsel = lane & 7;
        const float zi_g = __shfl_sync(0xffffffffu, r, bsel);
        const float zf_g = __shfl_sync(0xffffffffu, r, bsel + 8);
        const float zg_g = __shfl_sync(0xffffffffu, r, bsel + 16);
        const float zo_g = __shfl_sync(0xffffffffu, r, bsel + 24);

        if (lane < 8) {
            const float zi = zi_g + xpi;
            const float zf = zf_g + xpf;
            const float zg = zg_g + xpg;
            const float zo = zo_g + xpo;
            const float ig = 1.f / (1.f + __expf(-zi));
            const float fg = 1.f / (1.f + __expf(-zf));
            const float gg = tanhf(zg);
            const float og = 1.f / (1.f + __expf(-zo));
            const float cn = fg * cr + ig * gg;
            cr = cn;
            const float hn = og * tanhf(cn);
            hout[cidx] = hn;
            if (y) *y = hn;
        }
        if (j + 1 < nsteps) grid_barrier();
    }
    if (lane < 8) c[cidx] = cr;   // publish final cell state (used by concat)
}

// ---------------- bf16-split NT GEMM via mma.sync, cp.async, 1 sync/tile ------
#define LDSM4(d0,d1,d2,d3,addr) \
    asm volatile("ldmatrix.sync.aligned.m8n8.x4.shared.b16 {%0,%1,%2,%3}, [%4];" \
                 : "=r"(d0),"=r"(d1),"=r"(d2),"=r"(d3) : "r"(addr))
#define LDSM2(d0,d1,addr) \
    asm volatile("ldmatrix.sync.aligned.m8n8.x2.shared.b16 {%0,%1}, [%2];" \
                 : "=r"(d0),"=r"(d1) : "r"(addr))
#define MMA16816(c0,c1,c2,c3,a0,a1,a2,a3,b0,b1) \
    asm volatile("mma.sync.aligned.m16n8k16.row.col.f32.bf16.bf16.f32 " \
                 "{%0,%1,%2,%3},{%4,%5,%6,%7},{%8,%9},{%0,%1,%2,%3};" \
                 : "+f"(c0),"+f"(c1),"+f"(c2),"+f"(c3) \
                 : "r"(a0),"r"(a1),"r"(a2),"r"(a3),"r"(b0),"r"(b1))
#define CP16(dst, src) \
    asm volatile("cp.async.cg.shared.global [%0], [%1], 16;" \
                 :: "r"(dst), "l"(src) : "memory")
#define CP_COMMIT() asm volatile("cp.async.commit_group;" ::: "memory")
#define CP_WAIT0()  asm volatile("cp.async.wait_group 0;" ::: "memory")

#define SPAD 40
#define TILE_B (128 * SPAD * 2)          // bytes per array tile (10240)
#define STAGE_B (4 * TILE_B)             // bytes per stage (40960)
#define GEMM_SMEM (2 * STAGE_B)          // 81920

__device__ __forceinline__ void store_c(float* __restrict__ C, int m, int cc,
                                        float v0, float v1, int M, int N, int fcmode) {
    if (m >= M) return;
    float2 v; v.x = v0; v.y = v1;
    if (fcmode) {
        const int b = m & 15, t = (m >> 4) + 1;
        *(float2*)&C[(size_t)b * T_LEN * VOCAB + (size_t)t * VOCAB + cc] = v;
    } else {
        *(float2*)&C[(size_t)m * N + cc] = v;
    }
}

__global__ void __launch_bounds__(256, 2)
gemm_bf16x3_kernel(const __nv_bfloat16* __restrict__ Ah, const __nv_bfloat16* __restrict__ Al,
                   const __nv_bfloat16* __restrict__ Bh, const __nv_bfloat16* __restrict__ Bl,
                   const float* __restrict__ bias, float* __restrict__ C,
                   int M, int N, int K, int fcmode) {
    extern __shared__ __nv_bfloat16 sm[];  // [2 stages][4 arrays][128*SPAD]
    const int tid = threadIdx.x, warp = tid >> 5, lane = tid & 31;
    const int wm = warp >> 2, wn = warp & 3;
    const int m0 = blockIdx.y * 128, n0 = blockIdx.x * 128;
    const int lrow = tid >> 2;
    const int lcol = (tid & 3) << 3;

    const uint32_t smbase = (uint32_t)__cvta_generic_to_shared(sm);

    float acc[4][4][4];
#pragma unroll
    for (int i = 0; i < 4; ++i)
#pragma unroll
        for (int j = 0; j < 4; ++j)
#pragma unroll
            for (int q = 0; q < 4; ++q) acc[i][j][q] = 0.f;

    const int a_row = wm * 64 + (lane & 15);
    const int a_csel = (lane >> 4) << 3;
    const int b_row = wn * 32 + (lane & 7);
    const int b_csel = lane & 8;
    const int NT = K >> 5;

    auto issue_stage = [&](int kt, int s) {
        const int kc = kt << 5;
        const uint32_t stg = smbase + (uint32_t)(s * STAGE_B);
#pragma unroll
        for (int i = 0; i < 2; ++i) {
            const int r = lrow + i * 64;
            const size_t ga = (size_t)(m0 + r) * K + kc + lcol;
            const size_t gb = (size_t)(n0 + r) * K + kc + lcol;
            const uint32_t so = (uint32_t)(r * SPAD + lcol) * 2;
            CP16(stg + 0 * TILE_B + so, Ah + ga);
            CP16(stg + 1 * TILE_B + so, Al + ga);
            CP16(stg + 2 * TILE_B + so, Bh + gb);
            CP16(stg + 3 * TILE_B + so, Bl + gb);
        }
    };

    issue_stage(0, 0);
    CP_COMMIT();

    for (int kt = 0; kt < NT; ++kt) {
        const int s = kt & 1;
        CP_WAIT0();          // this warp's copies into stage s complete
        __syncthreads();     // all warps' copies done; all done reading s^1
        if (kt + 1 < NT) {   // safe to overwrite s^1 now
            issue_stage(kt + 1, s ^ 1);
            CP_COMMIT();
        }
        const uint32_t stg = smbase + (uint32_t)(s * STAGE_B);
#pragma unroll
        for (int h = 0; h < 2; ++h) {
            const int kk = h << 4;
            uint32_t afh[4][4], afl[4][4], bfh[4][2], bfl[4][2];
#pragma unroll
            for (int mi = 0; mi < 4; ++mi) {
                const uint32_t off = (uint32_t)(((a_row + mi * 16) * SPAD + kk + a_csel) * 2);
                LDSM4(afh[mi][0], afh[mi][1], afh[mi][2], afh[mi][3], stg + 0 * TILE_B + off);
                LDSM4(afl[mi][0], afl[mi][1], afl[mi][2], afl[mi][3], stg + 1 * TILE_B + off);
            }
#pragma unroll
            for (int ni = 0; ni < 4; ++ni) {
                const uint32_t off = (uint32_t)(((b_row + ni * 8) * SPAD + kk + b_csel) * 2);
                LDSM2(bfh[ni][0], bfh[ni][1], stg + 2 * TILE_B + off);
                LDSM2(bfl[ni][0], bfl[ni][1], stg + 3 * TILE_B + off);
            }
#pragma unroll
            for (int mi = 0; mi < 4; ++mi)
#pragma unroll
                for (int ni = 0; ni < 4; ++ni) {
                    float* c4 = acc[mi][ni];
                    MMA16816(c4[0], c4[1], c4[2], c4[3],
                             afh[mi][0], afh[mi][1], afh[mi][2], afh[mi][3],
                             bfh[ni][0], bfh[ni][1]);
                    MMA16816(c4[0], c4[1], c4[2], c4[3],
                             afh[mi][0], afh[mi][1], afh[mi][2], afh[mi][3],
                             bfl[ni][0], bfl[ni][1]);
                    MMA16816(c4[0], c4[1], c4[2], c4[3],
                             afl[mi][0], afl[mi][1], afl[mi][2], afl[mi][3],
                             bfh[ni][0], bfh[ni][1]);
                }
        }
    }

    const int g = lane >> 2, tc = lane & 3;
#pragma unroll
    for (int mi = 0; mi < 4; ++mi) {
#pragma unroll
        for (int ni = 0; ni < 4; ++ni) {
            const int r0 = m0 + wm * 64 + mi * 16 + g;
            const int cc = n0 + wn * 32 + ni * 8 + tc * 2;
            const float bb0 = bias[cc], bb1 = bias[cc + 1];
            store_c(C, r0,     cc, acc[mi][ni][0] + bb0, acc[mi][ni][1] + bb1, M, N, fcmode);
            store_c(C, r0 + 8, cc, acc[mi][ni][2] + bb0, acc[mi][ni][3] + bb1, M, N, fcmode);
        }
    }
}

// encoder [dir][b][512] -> decoder [b][1024]
__global__ void concat_hc_kernel(const float* __restrict__ hsrc, const float* __restrict__ csrc,
                                 float* __restrict__ hdst, float* __restrict__ cdst) {
    const int idx = blockIdx.x * 256 + threadIdx.x;
    const int b = idx >> 10, col = idx & 1023;
    const int dir = col >> 9, u = col & 511;
    const int s = dir * 8192 + b * 512 + u;
    hdst[idx] = hsrc[s];
    cdst[idx] = csrc[s];
}

__global__ void zero_t0_kernel(float* __restrict__ out) {
    const int idx = blockIdx.x * 256 + threadIdx.x;
    if (idx < 16 * VOCAB) {
        const int b = idx / VOCAB, v = idx - b * VOCAB;
        out[(size_t)b * T_LEN * VOCAB + v] = 0.f;
    }
}

// ---------------- driver ----------------
extern "C" void kernel_launch(void* const* d_in, const int* in_sizes, int n_in,
                              void* d_out, int out_size) {
    (void)in_sizes; (void)n_in; (void)out_size;
    const int*   src       = (const int*)d_in[0];
    const int*   tgt       = (const int*)d_in[1];
    const float* enc_embed = (const float*)d_in[3];
    const float* enc_Wih   = (const float*)d_in[4];
    const float* enc_Whh   = (const float*)d_in[5];
    const float* enc_b     = (const float*)d_in[6];
    const float* dec_embed = (const float*)d_in[7];
    const float* dec_Wih   = (const float*)d_in[8];
    const float* dec_Whh   = (const float*)d_in[9];
    const float* dec_b     = (const float*)d_in[10];
    const float* fc_W      = (const float*)d_in[11];
    const float* fc_b      = (const float*)d_in[12];
    float* out = (float*)d_out;

    float *x, *xp, *y, *h0s, *h1s, *hA, *hB, *eC, *dA, *dB, *dC, *dD, *c0, *c1;
    __nv_bfloat16 *Ah, *Al, *Wh, *Wl;
    cudaGetSymbolAddress((void**)&x, g_x);
    cudaGetSymbolAddress((void**)&xp, g_xproj);
    cudaGetSymbolAddress((void**)&y, g_y);
    cudaGetSymbolAddress((void**)&h0s, g_h0seq);
    cudaGetSymbolAddress((void**)&h1s, g_h1seq);
    cudaGetSymbolAddress((void**)&hA, g_hA);
    cudaGetSymbolAddress((void**)&hB, g_hB);
    cudaGetSymbolAddress((void**)&eC, g_encC);
    cudaGetSymbolAddress((void**)&dA, g_dhA);
    cudaGetSymbolAddress((void**)&dB, g_dhB);
    cudaGetSymbolAddress((void**)&dC, g_dhC);
    cudaGetSymbolAddress((void**)&dD, g_dhD);
    cudaGetSymbolAddress((void**)&c0, g_dc0);
    cudaGetSymbolAddress((void**)&c1, g_dc1);
    cudaGetSymbolAddress((void**)&Ah, g_Ah);
    cudaGetSymbolAddress((void**)&Al, g_Al);
    cudaGetSymbolAddress((void**)&Wh, g_Wh);
    cudaGetSymbolAddress((void**)&Wl, g_Wl);

    cudaFuncSetAttribute(lstm_chain_kernel<512, 2>,
                         cudaFuncAttributeMaxDynamicSharedMemorySize, 32768);
    cudaFuncSetAttribute(lstm_chain_kernel<1024, 1>,
                         cudaFuncAttributeMaxDynamicSharedMemorySize, 65536);
    cudaFuncSetAttribute(gemm_bf16x3_kernel,
                         cudaFuncAttributeMaxDynamicSharedMemorySize, GEMM_SMEM);

    auto splitN = [](const float* s, __nv_bfloat16* h, __nv_bfloat16* l, int n) {
        int n2 = n >> 1;
        split_kernel<<<(n2 + 255) / 256, 256>>>((const float2*)s,
                                                (__nv_bfloat162*)h, (__nv_bfloat162*)l, n2);
    };

    // ===== Encoder =====
    enc_embed_kernel<<<2048, 256>>>(enc_embed, src, x);
    for (int l = 0; l < 2; ++l) {
        cudaMemsetAsync(hA, 0, 16384 * sizeof(float));
        cudaMemsetAsync(eC, 0, 16384 * sizeof(float));
        const float* Ain = (l == 0) ? x : y;
        splitN(Ain, Ah, Al, 2048 * 1024);
        splitN(enc_Wih + (size_t)l * 4096 * 1024, Wh, Wl, 4096 * 1024);
        gemm_bf16x3_kernel<<<dim3(32, 16), 256, GEMM_SMEM>>>(
            Ah, Al, Wh, Wl, enc_b + l * 4096, xp, 2048, 4096, 1024, 0);
        const float* Whh_l = enc_Whh + (size_t)l * 2 * 2048 * 512;
        lstm_chain_kernel<512, 2><<<128, 512, 32768>>>(
            Whh_l, hA, hB, eC, xp, (l == 0) ? y : nullptr, 128);
        float* hdst = (l == 0) ? dA : dC;
        float* cdst = (l == 0) ? c0 : c1;
        concat_hc_kernel<<<64, 256>>>(hA, eC, hdst, cdst);
    }

    // ===== Decoder =====
    dec_embed_kernel<<<2032, 256>>>(dec_embed, tgt, x);
    // layer 0
    splitN(x, Ah, Al, 2032 * 1024);
    splitN(dec_Wih, Wh, Wl, 4096 * 1024);
    gemm_bf16x3_kernel<<<dim3(32, 16), 256, GEMM_SMEM>>>(
        Ah, Al, Wh, Wl, dec_b, xp, 2032, 4096, 1024, 0);
    lstm_chain_kernel<1024, 1><<<128, 512, 65536>>>(
        dec_Whh, dA, dB, c0, xp, h0s, 127);
    // layer 1
    splitN(h0s, Ah, Al, 2032 * 1024);
    splitN(dec_Wih + (size_t)4096 * 1024, Wh, Wl, 4096 * 1024);
    gemm_bf16x3_kernel<<<dim3(32, 16), 256, GEMM_SMEM>>>(
        Ah, Al, Wh, Wl, dec_b + 4096, xp, 2032, 4096, 1024, 0);
    lstm_chain_kernel<1024, 1><<<128, 512, 65536>>>(
        dec_Whh + (size_t)4096 * 1024, dC, dD, c1, xp, h1s, 127);

    // ===== Output =====
    zero_t0_kernel<<<2000, 256>>>(out);
    splitN(h1s, Ah, Al, 2032 * 1024);
    splitN(fc_W, Wh, Wl, 32000 * 1024);
    gemm_bf16x3_kernel<<<dim3(250, 16), 256, GEMM_SMEM>>>(
        Ah, Al, Wh, Wl, fc_b, out, 2032, VOCAB, 1024, 1);
}